// round 10
// baseline (speedup 1.0000x reference)
#include <cuda_runtime.h>
#include <cstdint>

#define NB   8
#define NA   25200
#define NC   80
#define NTOP 1000
#define NBINS 4096
#define CAP  6144
#define NTILE 32     // ceil(NTOP/32)
#define NPAIR 528    // NTILE*(NTILE+1)/2 upper-tri tiles
#define APW  16      // anchors per warp in k_conf (16 | 25200: no batch crossing)

#define GRID_WAIT()  asm volatile("griddepcontrol.wait;" ::: "memory")
#define GRID_TRIG()  asm volatile("griddepcontrol.launch_dependents;" ::: "memory")

// -------------------- scratch (device globals; no allocation) --------------------
__device__ unsigned long long g_selkey[NB * NA];   // (bits(1-masked)<<32) | (anchor<<7) | cls
__device__ int                g_hist[NB * NBINS];  // zero at load; k_mega re-zeroes each replay
__device__ float              g_topv[NB * NTOP];
__device__ float              g_clsf[NB * NTOP];
__device__ float4             g_tb[NB * NTOP];
__device__ float4             g_ob[NB * NTOP];
__device__ unsigned           g_maskbits[NB * NTOP * 32]; // lower-tri words stay 0 forever
__device__ unsigned           g_rowflag[NB * 32];

// -------------------- kernel 1: conf/argmax, 16 anchors/warp for MLP=16 --------------------
__global__ __launch_bounds__(256) void k_conf(const float* __restrict__ scores) {
    int gwarp = (blockIdx.x * 256 + threadIdx.x) >> 5;   // global warp id
    int lane  = threadIdx.x & 31;
    int abase = gwarp * APW;                              // first anchor (b*NA + a flat)
    const float4* s4 = (const float4*)scores;

    // front-batched loads: 16 independent coalesced LDG.128 (20 lanes each)
    float4 v[APW];
#pragma unroll
    for (int k = 0; k < APW; k++) {
        v[k] = make_float4(0.f, 0.f, 0.f, 0.f);
        if (lane < 20) v[k] = s4[(abase + k) * 20 + lane];
    }

    // per-anchor reductions (independent chains; warp-uniform results)
    unsigned long long key_sel = 0;
    unsigned hidx_sel = 0;
    int b = abase / NA;                                   // APW | NA: no batch crossing
#pragma unroll
    for (int k = 0; k < APW; k++) {
        unsigned b0 = __float_as_uint(v[k].x);
        unsigned b1 = __float_as_uint(v[k].y);
        unsigned b2 = __float_as_uint(v[k].z);
        unsigned b3 = __float_as_uint(v[k].w);
        unsigned mx = b0 > b1 ? b0 : b1;
        unsigned m2 = b2 > b3 ? b2 : b3;
        if (m2 > mx) mx = m2;
        unsigned wmx = __reduce_max_sync(0xffffffffu, mx);   // scores nonneg: uint order == float order
        unsigned cand = 0xFFu;
        if (b3 == wmx) cand = 4u * lane + 3u;
        if (b2 == wmx) cand = 4u * lane + 2u;
        if (b1 == wmx) cand = 4u * lane + 1u;
        if (b0 == wmx) cand = 4u * lane + 0u;
        cand = __reduce_min_sync(0xffffffffu, cand);         // smallest class among maxima (jnp.argmax)

        // warp-uniform key math
        float conf = __uint_as_float(wmx);
        float m    = (conf >= 0.5f) ? conf : -1.0f;
        float t    = 1.0f - m;                               // exact (Sterbenz) for m in [0.5,1]
        unsigned tb = __float_as_uint(t);
        int a = (abase + k) - b * NA;
        unsigned long long key = ((unsigned long long)tb << 32) | ((unsigned)(a << 7)) | cand;
        if (lane == k) { key_sel = key; hidx_sel = (unsigned)(b * NBINS) + (tb >> 20); }
    }

    if (lane < APW) {
        g_selkey[abase + lane] = key_sel;                    // coalesced 128B STG
        atomicAdd(&g_hist[hidx_sel], 1);
    }
    GRID_TRIG();
}

// -------------------- kernel 2: mega (decide + bin-grouped compact + per-bin rank + gather) --------------------
#define MEGA_W_CAND 0
#define MEGA_W_PRE  12288
#define MEGA_W_CNT  16384
#define MEGA_W_WSUM 20480
#define MEGA_W_SCAL 20512
#define MEGA_SMEM_WORDS 20516
__global__ __launch_bounds__(1024) void k_mega(const float* __restrict__ boxes) {
    extern __shared__ unsigned shm[];
    unsigned long long* cand = (unsigned long long*)(shm + MEGA_W_CAND);
    int* pre  = (int*)(shm + MEGA_W_PRE);
    int* cnt  = (int*)(shm + MEGA_W_CNT);
    int* wsum = (int*)(shm + MEGA_W_WSUM);
    int* scal = (int*)(shm + MEGA_W_SCAL);   // [0]=s_sel [1]=chosen [2]=m

    int b = blockIdx.x, t = threadIdx.x;
    int lane = t & 31, wid = t >> 5;

    GRID_WAIT();                               // k_conf's hist/selkey now visible

    if (t < 32) g_rowflag[b * 32 + t] = 0;    // reset for this replay's k_iou

    int hb = b * NBINS + t * 4;
    int h0 = g_hist[hb + 0], h1 = g_hist[hb + 1], h2 = g_hist[hb + 2], h3 = g_hist[hb + 3];
    g_hist[hb + 0] = 0; g_hist[hb + 1] = 0; g_hist[hb + 2] = 0; g_hist[hb + 3] = 0;
    int local = h0 + h1 + h2 + h3;

    int v = local;
#pragma unroll
    for (int off = 1; off < 32; off <<= 1) {
        int n = __shfl_up_sync(0xffffffffu, v, off);
        if (lane >= off) v += n;
    }
    if (lane == 31) wsum[wid] = v;
    if (t == 0) scal[0] = 1024;
    __syncthreads();
    if (t < 32) {
        int s = wsum[t];
        int is = s;
#pragma unroll
        for (int off = 1; off < 32; off <<= 1) {
            int n = __shfl_up_sync(0xffffffffu, is, off);
            if (t >= off) is += n;
        }
        wsum[t] = is - s;
    }
    __syncthreads();
    int incl = v + wsum[wid];
    int excl = incl - local;
    pre[t * 4 + 0] = excl;
    pre[t * 4 + 1] = excl + h0;
    pre[t * 4 + 2] = excl + h0 + h1;
    pre[t * 4 + 3] = excl + h0 + h1 + h2;
    cnt[t * 4 + 0] = 0; cnt[t * 4 + 1] = 0; cnt[t * 4 + 2] = 0; cnt[t * 4 + 3] = 0;
    if (excl < NTOP && incl >= NTOP) atomicMin(&scal[0], t);
    __syncthreads();
    if (t == scal[0]) {
        int bin, mm;
        if      (excl + h0 >= NTOP)           { bin = t * 4 + 0; mm = excl + h0; }
        else if (excl + h0 + h1 >= NTOP)      { bin = t * 4 + 1; mm = excl + h0 + h1; }
        else if (excl + h0 + h1 + h2 >= NTOP) { bin = t * 4 + 2; mm = excl + h0 + h1 + h2; }
        else                                  { bin = t * 4 + 3; mm = excl + local; }
        scal[1] = bin; scal[2] = mm;
    }
    __syncthreads();
    int chosen = scal[1];
    int m = scal[2]; if (m > CAP) m = CAP;

    const ulonglong2* keys2 = (const ulonglong2*)(g_selkey + (size_t)b * NA);
    for (int i = t; i < NA / 2; i += 1024) {
        ulonglong2 kk = keys2[i];
        int bin0 = (int)(kk.x >> 52);
        if (bin0 <= chosen) {
            int pos = pre[bin0] + atomicAdd(&cnt[bin0], 1);
            if (pos < CAP) cand[pos] = kk.x;
        }
        int bin1 = (int)(kk.y >> 52);
        if (bin1 <= chosen) {
            int pos = pre[bin1] + atomicAdd(&cnt[bin1], 1);
            if (pos < CAP) cand[pos] = kk.y;
        }
    }
    __syncthreads();

    const float4* bx4 = (const float4*)boxes;
    for (int e = t; e < m; e += 1024) {
        unsigned long long ke = cand[e];
        int bin = (int)(ke >> 52);
        int start = pre[bin];
        int end   = start + cnt[bin]; if (end > m) end = m;
        int rank  = start;
        for (int j = start; j < end; j++) rank += (cand[j] < ke) ? 1 : 0;
        if (rank < NTOP) {
            int a   = (int)((unsigned)(ke & 0xFFFFFFFFull) >> 7);
            int cls = (int)(ke & 127ull);
            float tt = __uint_as_float((unsigned)(ke >> 32));
            float vv = 1.0f - tt;                // bit-exact reconstruction of masked conf
            float cf = (float)cls;
            float4 bb = bx4[b * NA + a];
            int o = b * NTOP + rank;
            g_topv[o] = vv;
            g_clsf[o] = cf;
            g_tb[o]   = bb;
            float off = cf * 4096.0f;
            g_ob[o]   = make_float4(bb.x + off, bb.y + off, bb.z + off, bb.w + off);
        }
    }
    GRID_TRIG();
}

// -------------------- kernel 3: IoU upper-triangle tiles + zero-inter fast path --------------------
__global__ __launch_bounds__(256) void k_iou() {
    int b = blockIdx.y;
    __shared__ float4 sob[NTILE * 32];
    __shared__ float  sar[NTILE * 32];
    GRID_WAIT();                               // k_mega's g_ob/rowflag now visible
    for (int i = threadIdx.x; i < NTILE * 32; i += 256) {
        float4 q = (i < NTOP) ? g_ob[b * NTOP + i] : make_float4(0.f, 0.f, 0.f, 0.f);
        sob[i] = q;
        sar[i] = (q.z - q.x) * (q.w - q.y);
    }
    __syncthreads();

    int w = threadIdx.x >> 5, l = threadIdx.x & 31;
    int s = blockIdx.x * 8 + w;            // tile id in [0, 528)
    int TI = 0, rem = s;
    while (rem >= NTILE - TI) { rem -= NTILE - TI; TI++; }
    int TJ = TI + rem;

    int j = TJ * 32 + l;
    float4 bj   = sob[j];
    float areaj = sar[j];
    unsigned myword = 0;

#pragma unroll 1
    for (int ii = 0; ii < 32; ii++) {
        int i = TI * 32 + ii;
        float4 bi = sob[i];                // LDS broadcast
        float xx1 = fmaxf(bi.x, bj.x);
        float yy1 = fmaxf(bi.y, bj.y);
        float xx2 = fminf(bi.z, bj.z);
        float yy2 = fminf(bi.w, bj.w);
        float iw = fmaxf(xx2 - xx1, 0.0f);
        float ih = fmaxf(yy2 - yy1, 0.0f);
        bool candp = (iw > 0.0f) && (ih > 0.0f) && (j > i) && (j < NTOP) && (i < NTOP);
        unsigned any = __ballot_sync(0xffffffffu, candp);
        unsigned word = 0;
        if (any) {                          // warp-uniform: skip division when no intersection
            float inter = iw * ih;
            float u = sar[i] + areaj - inter + 1e-7f;
            bool sup = candp && ((inter / u) > 0.6f);   // exact div: match reference rounding
            word = __ballot_sync(0xffffffffu, sup);
        }
        if (l == ii) myword = word;
    }

    int i_row = TI * 32 + l;
    bool valid_row = (i_row < NTOP);
    if (valid_row) g_maskbits[((size_t)b * NTOP + i_row) * 32 + TJ] = myword;
    unsigned fl = __ballot_sync(0xffffffffu, (myword != 0) && valid_row);
    if (l == 0 && fl) atomicOr(&g_rowflag[b * 32 + TI], fl);
    GRID_TRIG();
}

// -------------------- kernel 4: sparse greedy scan + output (latency-overlapped) --------------------
// dyn smem (words): sst 1000*33 | slist 1024 | svalid 32 | srem 32 | scount 4
#define NMS_W_SST   0
#define NMS_W_LIST  33000
#define NMS_W_VAL   34024
#define NMS_W_REM   34056
#define NMS_W_CNT   34088
#define NMS_SMEM_WORDS 34092
__global__ __launch_bounds__(1024) void k_nms(float* __restrict__ out) {
    extern __shared__ unsigned sh[];
    unsigned* sst    = sh + NMS_W_SST;
    int*      slist  = (int*)(sh + NMS_W_LIST);
    unsigned* svalid = sh + NMS_W_VAL;
    unsigned* srem   = sh + NMS_W_REM;
    int*      scount = (int*)(sh + NMS_W_CNT);

    int b = blockIdx.x, t = threadIdx.x;

    GRID_WAIT();                               // k_iou's maskbits/rowflag now visible

    // independent register loads issue early (overlap list build)
    float  v  = (t < NTOP) ? g_topv[b * NTOP + t] : -1.0f;
    float4 bb = make_float4(0.f, 0.f, 0.f, 0.f);
    float  cf = 0.0f;
    if (t < NTOP) { bb = g_tb[b * NTOP + t]; cf = g_clsf[b * NTOP + t]; }

    unsigned wd = __ballot_sync(0xffffffffu, v >= 0.5f);
    if ((t & 31) == 0) svalid[t >> 5] = wd;

    // warp 0: build ordered list of flagged rows
    if (t < 32) {
        int l = t;
        unsigned flag = g_rowflag[b * 32 + l];
        int c = __popc(flag);
        int pr = c;
#pragma unroll
        for (int off = 1; off < 32; off <<= 1) {
            int n = __shfl_up_sync(0xffffffffu, pr, off);
            if (l >= off) pr += n;
        }
        int base = pr - c;
        int total = __shfl_sync(0xffffffffu, pr, 31);
        unsigned f = flag;
        int p = base;
        while (f) {
            int ii = __ffs(f) - 1; f &= f - 1;
            slist[p++] = l * 32 + ii;
        }
        if (l == 0) scount[0] = total;
    }
    __syncthreads();

    // stage flagged rows (padded stride 33)
    int S = scount[0];
    for (int idx = t; idx < S * 32; idx += 1024) {
        int r = idx >> 5, ww = idx & 31;
        sst[r * 33 + ww] = g_maskbits[((size_t)b * NTOP + slist[r]) * 32 + ww];
    }
    __syncthreads();

    // warp 0: serial greedy scan over flagged rows (exact: unflagged rows are no-ops)
    if (t < 32) {
        int l = t;
        unsigned removed_l = 0;
        for (int s = 0; s < S; s++) {
            int i = slist[s];
            unsigned rowword = sst[s * 33 + l];
            int g = i >> 5, ii = i & 31;
            unsigned rw = __shfl_sync(0xffffffffu, removed_l, g);
            bool alive = ((svalid[g] >> ii) & 1u) && !((rw >> ii) & 1u);
            if (alive) removed_l |= rowword;
        }
        srem[l] = removed_l;
    }
    __syncthreads();

    if (t < NTOP) {
        bool keep = (v >= 0.5f) && !((srem[t >> 5] >> (t & 31)) & 1u);
        float fk = keep ? 1.0f : 0.0f;
        int o = b * NTOP + t;
        float4 o0 = make_float4(v * fk, bb.x * fk, bb.y * fk, bb.z * fk);
        float4 o1 = make_float4(bb.w * fk, (float)b * fk, cf * fk, 0.0f);
        ((float4*)out)[o * 2 + 0] = o0;
        ((float4*)out)[o * 2 + 1] = o1;
    }
}

// -------------------- launch: PDL-chained, single stream, allocation-free --------------------
static void launch_pdl(const void* func, dim3 grid, dim3 block, size_t smem,
                       void** args, bool dependent) {
    cudaLaunchConfig_t cfg = {};
    cfg.gridDim = grid;
    cfg.blockDim = block;
    cfg.dynamicSmemBytes = smem;
    cfg.stream = 0;
    cudaLaunchAttribute attr[1];
    if (dependent) {
        attr[0].id = cudaLaunchAttributeProgrammaticStreamSerialization;
        attr[0].val.programmaticStreamSerializationAllowed = 1;
        cfg.attrs = attr;
        cfg.numAttrs = 1;
    }
    cudaLaunchKernelExC(&cfg, func, args);
}

extern "C" void kernel_launch(void* const* d_in, const int* in_sizes, int n_in,
                              void* d_out, int out_size) {
    const float* boxes  = (const float*)d_in[0];
    const float* scores = (const float*)d_in[1];
    if (n_in >= 2 && in_sizes[0] > in_sizes[1]) {
        const float* tmp = boxes; boxes = scores; scores = tmp;
    }
    float* out = (float*)d_out;

    cudaFuncSetAttribute(k_mega, cudaFuncAttributeMaxDynamicSharedMemorySize,
                         MEGA_SMEM_WORDS * 4);
    cudaFuncSetAttribute(k_nms, cudaFuncAttributeMaxDynamicSharedMemorySize,
                         NMS_SMEM_WORDS * 4);

    void* a_conf[] = { (void*)&scores };
    void* a_mega[] = { (void*)&boxes };
    void* a_nms[]  = { (void*)&out };

    launch_pdl((const void*)k_conf, dim3((NB * NA) / (APW * 8)), dim3(256), 0, a_conf, false);
    launch_pdl((const void*)k_mega, dim3(NB), dim3(1024), MEGA_SMEM_WORDS * 4, a_mega, true);
    launch_pdl((const void*)k_iou,  dim3(NPAIR / 8, NB), dim3(256), 0, nullptr, true);
    launch_pdl((const void*)k_nms,  dim3(NB), dim3(1024), NMS_SMEM_WORDS * 4, a_nms, true);
    (void)out_size;
}

// round 11
// speedup vs baseline: 1.0057x; 1.0057x over previous
#include <cuda_runtime.h>
#include <cstdint>

#define NB   8
#define NA   25200
#define NC   80
#define NTOP 1000
#define NBINS 4096
#define CAP  6144
#define NTILE 32     // ceil(NTOP/32)
#define NPAIR 528    // NTILE*(NTILE+1)/2 upper-tri tiles

#define CBLK  256    // threads == anchors per k_conf block
#define CF4   20     // float4 per anchor (80 floats)
#define PADF4 21     // padded float4 stride (336B) -> conflict-free LDS
#define CONF_SMEM (CBLK * PADF4 * 16)

#define GRID_WAIT()  asm volatile("griddepcontrol.wait;" ::: "memory")
#define GRID_TRIG()  asm volatile("griddepcontrol.launch_dependents;" ::: "memory")

// -------------------- scratch (device globals; no allocation) --------------------
__device__ unsigned long long g_selkey[NB * NA];   // (bits(1-masked)<<32) | (anchor<<7) | cls
__device__ int                g_hist[NB * NBINS];  // zero at load; k_mega re-zeroes each replay
__device__ float              g_topv[NB * NTOP];
__device__ float              g_clsf[NB * NTOP];
__device__ float4             g_tb[NB * NTOP];
__device__ float4             g_ob[NB * NTOP];
__device__ unsigned           g_maskbits[NB * NTOP * 32]; // lower-tri words stay 0 forever
__device__ unsigned           g_rowflag[NB * 32];

// -------------------- kernel 1: conf/argmax, thread-per-anchor via smem staging --------------------
__global__ __launch_bounds__(256) void k_conf(const float* __restrict__ scores) {
    extern __shared__ float4 ss[];                 // CBLK*PADF4 float4 = 86016 B
    const float4* s4 = (const float4*)scores;
    int t = threadIdx.x;
    int blockbase = blockIdx.x * CBLK;             // first flat anchor of this block
    const int total = NB * NA;

    // phase A: coalesced global -> padded smem (4 rounds of 5 independent LDG.128)
#pragma unroll
    for (int i = 0; i < CF4; i += 5) {
        float4 v[5];
#pragma unroll
        for (int k = 0; k < 5; k++) {
            int g = (i + k) * CBLK + t;            // block-local float4 chunk
            int anc = blockbase + g / CF4;
            v[k] = (anc < total) ? s4[(size_t)blockbase * CF4 + g]
                                 : make_float4(0.f, 0.f, 0.f, 0.f);
        }
#pragma unroll
        for (int k = 0; k < 5; k++) {
            int g = (i + k) * CBLK + t;
            ss[(g / CF4) * PADF4 + (g % CF4)] = v[k];
        }
    }
    __syncthreads();

    // phase B: thread t reduces anchor (blockbase + t) entirely in registers
    int anchor = blockbase + t;
    const float4* arow = ss + t * PADF4;
    unsigned long long best = 0;                   // any real key > 0
#pragma unroll
    for (int q = 0; q < CF4; q++) {
        float4 w = arow[q];
        int c = 4 * q;
        // key = valbits<<8 | (255-cls): max key == max val, tie -> smallest class (jnp.argmax)
        unsigned long long k0 = ((unsigned long long)__float_as_uint(w.x) << 8) | (unsigned)(255 - c);
        unsigned long long k1 = ((unsigned long long)__float_as_uint(w.y) << 8) | (unsigned)(254 - c);
        unsigned long long k2 = ((unsigned long long)__float_as_uint(w.z) << 8) | (unsigned)(253 - c);
        unsigned long long k3 = ((unsigned long long)__float_as_uint(w.w) << 8) | (unsigned)(252 - c);
        unsigned long long m01 = k0 > k1 ? k0 : k1;
        unsigned long long m23 = k2 > k3 ? k2 : k3;
        unsigned long long mq  = m01 > m23 ? m01 : m23;
        if (mq > best) best = mq;
    }

    unsigned hidx = 0xFFFFFFFFu;
    if (anchor < total) {
        unsigned valbits = (unsigned)(best >> 8);
        int      cls     = 255 - (int)(best & 0xFFull);
        float conf = __uint_as_float(valbits);     // scores nonneg: uint order == float order
        float m    = (conf >= 0.5f) ? conf : -1.0f;
        float tv   = 1.0f - m;                     // exact (Sterbenz) for m in [0.5,1]
        unsigned tb = __float_as_uint(tv);
        int b = anchor / NA;
        int a = anchor - b * NA;
        g_selkey[anchor] = ((unsigned long long)tb << 32) | ((unsigned)(a << 7)) | (unsigned)cls;
        hidx = (unsigned)(b * NBINS) + (tb >> 20);
    }
    // warp-aggregated histogram atomics (collapses the hot masked bin)
    unsigned grp = __match_any_sync(0xffffffffu, hidx);
    int leader = __ffs(grp) - 1;
    if ((t & 31) == leader && hidx != 0xFFFFFFFFu)
        atomicAdd(&g_hist[hidx], __popc(grp));
    GRID_TRIG();
}

// -------------------- kernel 2: mega (decide + bin-grouped compact + per-bin rank + gather) --------------------
#define MEGA_W_CAND 0
#define MEGA_W_PRE  12288
#define MEGA_W_CNT  16384
#define MEGA_W_WSUM 20480
#define MEGA_W_SCAL 20512
#define MEGA_SMEM_WORDS 20516
__global__ __launch_bounds__(1024) void k_mega(const float* __restrict__ boxes) {
    extern __shared__ unsigned shm[];
    unsigned long long* cand = (unsigned long long*)(shm + MEGA_W_CAND);
    int* pre  = (int*)(shm + MEGA_W_PRE);
    int* cnt  = (int*)(shm + MEGA_W_CNT);
    int* wsum = (int*)(shm + MEGA_W_WSUM);
    int* scal = (int*)(shm + MEGA_W_SCAL);   // [0]=s_sel [1]=chosen [2]=m

    int b = blockIdx.x, t = threadIdx.x;
    int lane = t & 31, wid = t >> 5;

    GRID_WAIT();                               // k_conf's hist/selkey now visible

    if (t < 32) g_rowflag[b * 32 + t] = 0;    // reset for this replay's k_iou

    int hb = b * NBINS + t * 4;
    int h0 = g_hist[hb + 0], h1 = g_hist[hb + 1], h2 = g_hist[hb + 2], h3 = g_hist[hb + 3];
    g_hist[hb + 0] = 0; g_hist[hb + 1] = 0; g_hist[hb + 2] = 0; g_hist[hb + 3] = 0;
    int local = h0 + h1 + h2 + h3;

    int v = local;
#pragma unroll
    for (int off = 1; off < 32; off <<= 1) {
        int n = __shfl_up_sync(0xffffffffu, v, off);
        if (lane >= off) v += n;
    }
    if (lane == 31) wsum[wid] = v;
    if (t == 0) scal[0] = 1024;
    __syncthreads();
    if (t < 32) {
        int s = wsum[t];
        int is = s;
#pragma unroll
        for (int off = 1; off < 32; off <<= 1) {
            int n = __shfl_up_sync(0xffffffffu, is, off);
            if (t >= off) is += n;
        }
        wsum[t] = is - s;
    }
    __syncthreads();
    int incl = v + wsum[wid];
    int excl = incl - local;
    pre[t * 4 + 0] = excl;
    pre[t * 4 + 1] = excl + h0;
    pre[t * 4 + 2] = excl + h0 + h1;
    pre[t * 4 + 3] = excl + h0 + h1 + h2;
    cnt[t * 4 + 0] = 0; cnt[t * 4 + 1] = 0; cnt[t * 4 + 2] = 0; cnt[t * 4 + 3] = 0;
    if (excl < NTOP && incl >= NTOP) atomicMin(&scal[0], t);
    __syncthreads();
    if (t == scal[0]) {
        int bin, mm;
        if      (excl + h0 >= NTOP)           { bin = t * 4 + 0; mm = excl + h0; }
        else if (excl + h0 + h1 >= NTOP)      { bin = t * 4 + 1; mm = excl + h0 + h1; }
        else if (excl + h0 + h1 + h2 >= NTOP) { bin = t * 4 + 2; mm = excl + h0 + h1 + h2; }
        else                                  { bin = t * 4 + 3; mm = excl + local; }
        scal[1] = bin; scal[2] = mm;
    }
    __syncthreads();
    int chosen = scal[1];
    int m = scal[2]; if (m > CAP) m = CAP;

    const ulonglong2* keys2 = (const ulonglong2*)(g_selkey + (size_t)b * NA);
    for (int i = t; i < NA / 2; i += 1024) {
        ulonglong2 kk = keys2[i];
        int bin0 = (int)(kk.x >> 52);
        if (bin0 <= chosen) {
            int pos = pre[bin0] + atomicAdd(&cnt[bin0], 1);
            if (pos < CAP) cand[pos] = kk.x;
        }
        int bin1 = (int)(kk.y >> 52);
        if (bin1 <= chosen) {
            int pos = pre[bin1] + atomicAdd(&cnt[bin1], 1);
            if (pos < CAP) cand[pos] = kk.y;
        }
    }
    __syncthreads();

    const float4* bx4 = (const float4*)boxes;
    for (int e = t; e < m; e += 1024) {
        unsigned long long ke = cand[e];
        int bin = (int)(ke >> 52);
        int start = pre[bin];
        int end   = start + cnt[bin]; if (end > m) end = m;
        int rank  = start;
        for (int j = start; j < end; j++) rank += (cand[j] < ke) ? 1 : 0;
        if (rank < NTOP) {
            int a   = (int)((unsigned)(ke & 0xFFFFFFFFull) >> 7);
            int cls = (int)(ke & 127ull);
            float tt = __uint_as_float((unsigned)(ke >> 32));
            float vv = 1.0f - tt;                // bit-exact reconstruction of masked conf
            float cf = (float)cls;
            float4 bb = bx4[b * NA + a];
            int o = b * NTOP + rank;
            g_topv[o] = vv;
            g_clsf[o] = cf;
            g_tb[o]   = bb;
            float off = cf * 4096.0f;
            g_ob[o]   = make_float4(bb.x + off, bb.y + off, bb.z + off, bb.w + off);
        }
    }
    GRID_TRIG();
}

// -------------------- kernel 3: IoU upper-triangle tiles + zero-inter fast path --------------------
__global__ __launch_bounds__(256) void k_iou() {
    int b = blockIdx.y;
    __shared__ float4 sob[NTILE * 32];
    __shared__ float  sar[NTILE * 32];
    GRID_WAIT();                               // k_mega's g_ob/rowflag now visible
    for (int i = threadIdx.x; i < NTILE * 32; i += 256) {
        float4 q = (i < NTOP) ? g_ob[b * NTOP + i] : make_float4(0.f, 0.f, 0.f, 0.f);
        sob[i] = q;
        sar[i] = (q.z - q.x) * (q.w - q.y);
    }
    __syncthreads();

    int w = threadIdx.x >> 5, l = threadIdx.x & 31;
    int s = blockIdx.x * 8 + w;            // tile id in [0, 528)
    int TI = 0, rem = s;
    while (rem >= NTILE - TI) { rem -= NTILE - TI; TI++; }
    int TJ = TI + rem;

    int j = TJ * 32 + l;
    float4 bj   = sob[j];
    float areaj = sar[j];
    unsigned myword = 0;

#pragma unroll 1
    for (int ii = 0; ii < 32; ii++) {
        int i = TI * 32 + ii;
        float4 bi = sob[i];                // LDS broadcast
        float xx1 = fmaxf(bi.x, bj.x);
        float yy1 = fmaxf(bi.y, bj.y);
        float xx2 = fminf(bi.z, bj.z);
        float yy2 = fminf(bi.w, bj.w);
        float iw = fmaxf(xx2 - xx1, 0.0f);
        float ih = fmaxf(yy2 - yy1, 0.0f);
        bool candp = (iw > 0.0f) && (ih > 0.0f) && (j > i) && (j < NTOP) && (i < NTOP);
        unsigned any = __ballot_sync(0xffffffffu, candp);
        unsigned word = 0;
        if (any) {                          // warp-uniform: skip division when no intersection
            float inter = iw * ih;
            float u = sar[i] + areaj - inter + 1e-7f;
            bool sup = candp && ((inter / u) > 0.6f);   // exact div: match reference rounding
            word = __ballot_sync(0xffffffffu, sup);
        }
        if (l == ii) myword = word;
    }

    int i_row = TI * 32 + l;
    bool valid_row = (i_row < NTOP);
    if (valid_row) g_maskbits[((size_t)b * NTOP + i_row) * 32 + TJ] = myword;
    unsigned fl = __ballot_sync(0xffffffffu, (myword != 0) && valid_row);
    if (l == 0 && fl) atomicOr(&g_rowflag[b * 32 + TI], fl);
    GRID_TRIG();
}

// -------------------- kernel 4: sparse greedy scan + output (latency-overlapped) --------------------
// dyn smem (words): sst 1000*33 | slist 1024 | svalid 32 | srem 32 | scount 4
#define NMS_W_SST   0
#define NMS_W_LIST  33000
#define NMS_W_VAL   34024
#define NMS_W_REM   34056
#define NMS_W_CNT   34088
#define NMS_SMEM_WORDS 34092
__global__ __launch_bounds__(1024) void k_nms(float* __restrict__ out) {
    extern __shared__ unsigned sh[];
    unsigned* sst    = sh + NMS_W_SST;
    int*      slist  = (int*)(sh + NMS_W_LIST);
    unsigned* svalid = sh + NMS_W_VAL;
    unsigned* srem   = sh + NMS_W_REM;
    int*      scount = (int*)(sh + NMS_W_CNT);

    int b = blockIdx.x, t = threadIdx.x;

    GRID_WAIT();                               // k_iou's maskbits/rowflag now visible

    // independent register loads issue early (overlap list build)
    float  v  = (t < NTOP) ? g_topv[b * NTOP + t] : -1.0f;
    float4 bb = make_float4(0.f, 0.f, 0.f, 0.f);
    float  cf = 0.0f;
    if (t < NTOP) { bb = g_tb[b * NTOP + t]; cf = g_clsf[b * NTOP + t]; }

    unsigned wd = __ballot_sync(0xffffffffu, v >= 0.5f);
    if ((t & 31) == 0) svalid[t >> 5] = wd;

    // warp 0: build ordered list of flagged rows
    if (t < 32) {
        int l = t;
        unsigned flag = g_rowflag[b * 32 + l];
        int c = __popc(flag);
        int pr = c;
#pragma unroll
        for (int off = 1; off < 32; off <<= 1) {
            int n = __shfl_up_sync(0xffffffffu, pr, off);
            if (l >= off) pr += n;
        }
        int base = pr - c;
        int total = __shfl_sync(0xffffffffu, pr, 31);
        unsigned f = flag;
        int p = base;
        while (f) {
            int ii = __ffs(f) - 1; f &= f - 1;
            slist[p++] = l * 32 + ii;
        }
        if (l == 0) scount[0] = total;
    }
    __syncthreads();

    // stage flagged rows (padded stride 33)
    int S = scount[0];
    for (int idx = t; idx < S * 32; idx += 1024) {
        int r = idx >> 5, ww = idx & 31;
        sst[r * 33 + ww] = g_maskbits[((size_t)b * NTOP + slist[r]) * 32 + ww];
    }
    __syncthreads();

    // warp 0: serial greedy scan over flagged rows (exact: unflagged rows are no-ops)
    if (t < 32) {
        int l = t;
        unsigned removed_l = 0;
        for (int s = 0; s < S; s++) {
            int i = slist[s];
            unsigned rowword = sst[s * 33 + l];
            int g = i >> 5, ii = i & 31;
            unsigned rw = __shfl_sync(0xffffffffu, removed_l, g);
            bool alive = ((svalid[g] >> ii) & 1u) && !((rw >> ii) & 1u);
            if (alive) removed_l |= rowword;
        }
        srem[l] = removed_l;
    }
    __syncthreads();

    if (t < NTOP) {
        bool keep = (v >= 0.5f) && !((srem[t >> 5] >> (t & 31)) & 1u);
        float fk = keep ? 1.0f : 0.0f;
        int o = b * NTOP + t;
        float4 o0 = make_float4(v * fk, bb.x * fk, bb.y * fk, bb.z * fk);
        float4 o1 = make_float4(bb.w * fk, (float)b * fk, cf * fk, 0.0f);
        ((float4*)out)[o * 2 + 0] = o0;
        ((float4*)out)[o * 2 + 1] = o1;
    }
}

// -------------------- launch: PDL-chained, single stream, allocation-free --------------------
static void launch_pdl(const void* func, dim3 grid, dim3 block, size_t smem,
                       void** args, bool dependent) {
    cudaLaunchConfig_t cfg = {};
    cfg.gridDim = grid;
    cfg.blockDim = block;
    cfg.dynamicSmemBytes = smem;
    cfg.stream = 0;
    cudaLaunchAttribute attr[1];
    if (dependent) {
        attr[0].id = cudaLaunchAttributeProgrammaticStreamSerialization;
        attr[0].val.programmaticStreamSerializationAllowed = 1;
        cfg.attrs = attr;
        cfg.numAttrs = 1;
    }
    cudaLaunchKernelExC(&cfg, func, args);
}

extern "C" void kernel_launch(void* const* d_in, const int* in_sizes, int n_in,
                              void* d_out, int out_size) {
    const float* boxes  = (const float*)d_in[0];
    const float* scores = (const float*)d_in[1];
    if (n_in >= 2 && in_sizes[0] > in_sizes[1]) {
        const float* tmp = boxes; boxes = scores; scores = tmp;
    }
    float* out = (float*)d_out;

    cudaFuncSetAttribute(k_conf, cudaFuncAttributeMaxDynamicSharedMemorySize, CONF_SMEM);
    cudaFuncSetAttribute(k_mega, cudaFuncAttributeMaxDynamicSharedMemorySize,
                         MEGA_SMEM_WORDS * 4);
    cudaFuncSetAttribute(k_nms, cudaFuncAttributeMaxDynamicSharedMemorySize,
                         NMS_SMEM_WORDS * 4);

    void* a_conf[] = { (void*)&scores };
    void* a_mega[] = { (void*)&boxes };
    void* a_nms[]  = { (void*)&out };

    int conf_grid = (NB * NA + CBLK - 1) / CBLK;   // 788
    launch_pdl((const void*)k_conf, dim3(conf_grid), dim3(CBLK), CONF_SMEM, a_conf, false);
    launch_pdl((const void*)k_mega, dim3(NB), dim3(1024), MEGA_SMEM_WORDS * 4, a_mega, true);
    launch_pdl((const void*)k_iou,  dim3(NPAIR / 8, NB), dim3(256), 0, nullptr, true);
    launch_pdl((const void*)k_nms,  dim3(NB), dim3(1024), NMS_SMEM_WORDS * 4, a_nms, true);
    (void)out_size;
}